// round 7
// baseline (speedup 1.0000x reference)
#include <cuda_runtime.h>
#include <cstdint>

// DistMult forward scoring:
//   score[e] = sum_d h[src[e],d] * fwd_rel[etype[e],d] * h[dst[e],d]
// E = 640000, D = 128. Index arrays are int32 on device (JAX x64 disabled).
//
// R7: persistent warps + index software-pipelining.
//  - Single resident wave (152 SMs x 7 blocks x 8 warps), each warp loops
//    over ~19 edge-quads -> no tail waves, no 20K-block launch overhead.
//  - Next quad's src/dst/etype are prefetched at the top of each iteration,
//    removing the idx->row-load dependent chain (two L2 round trips, ~500cyc)
//    from the per-quad critical path.
//  - Keeps R6's cache split: h -> __ldcg (L2-only, no L1 thrash),
//    fwd_rel -> __ldg (L1-resident, 256KB with ~8.6 refs/row/SM).
//  - Layout: 8 lanes/edge, 4 edges/warp; each LDG.128 reads one full 128B
//    line per 8-lane group (minimal wavefronts: 12 lines/edge, irreducible).

#define EMB_DIM 128

__global__ __launch_bounds__(256, 7) void distmult_score_kernel(
    const float* __restrict__ h,
    const int* __restrict__ src,
    const int* __restrict__ dst,
    const int* __restrict__ etype,
    const float* __restrict__ fwd_rel,
    float* __restrict__ out,
    int n_edges)
{
    const int lane   = threadIdx.x & 31;
    const int group  = lane >> 3;   // 0..3 : edge within the quad
    const int sl     = lane & 7;    // 0..7 : sub-lane within the edge
    const int nwarps = (gridDim.x * blockDim.x) >> 5;
    const int nquads = (n_edges + 3) >> 2;

    int q = (blockIdx.x * blockDim.x + threadIdx.x) >> 5;
    if (q >= nquads) return;

    // Indices for the first quad (cold; later iterations use prefetched ones).
    int e      = q * 4 + group;
    bool valid = (e < n_edges);
    {
        const int ec = valid ? e : (n_edges - 1);
        e = e;  // keep original for the store
        // fallthrough into loop with s/d/t loaded below
    }
    int ec0 = valid ? e : (n_edges - 1);
    int s = __ldg(src + ec0);
    int d = __ldg(dst + ec0);
    int t = __ldg(etype + ec0);

    for (;;) {
        // ---- prefetch next quad's indices (uniform branch per warp) ----
        const int  qn   = q + nwarps;
        const bool more = (qn < nquads);
        int en = 0, sn = 0, dn = 0, tn = 0;
        bool vn = false;
        if (more) {
            en = qn * 4 + group;
            vn = (en < n_edges);
            const int enc = vn ? en : (n_edges - 1);
            sn = __ldg(src + enc);
            dn = __ldg(dst + enc);
            tn = __ldg(etype + enc);
        }

        // ---- current quad: 12 x LDG.128, fused triple-product dot ----
        const float4* __restrict__ hu =
            reinterpret_cast<const float4*>(h + (size_t)s * EMB_DIM);
        const float4* __restrict__ hv =
            reinterpret_cast<const float4*>(h + (size_t)d * EMB_DIM);
        const float4* __restrict__ wr =
            reinterpret_cast<const float4*>(fwd_rel + (size_t)t * EMB_DIM);

        float acc = 0.0f;
        #pragma unroll
        for (int j = 0; j < 4; j++) {
            const int idx = sl + j * 8;
            const float4 a = __ldcg(hu + idx);   // h: L2-only
            const float4 c = __ldcg(hv + idx);   // h: L2-only
            const float4 b = __ldg(wr + idx);    // rel: L1-resident
            float p = a.x * b.x * c.x;
            p = fmaf(a.y * b.y, c.y, p);
            p = fmaf(a.z * b.z, c.z, p);
            p = fmaf(a.w * b.w, c.w, p);
            acc += p;
        }

        // Reduce across the 8 sub-lanes of each group.
        acc += __shfl_xor_sync(0xffffffffu, acc, 4);
        acc += __shfl_xor_sync(0xffffffffu, acc, 2);
        acc += __shfl_xor_sync(0xffffffffu, acc, 1);

        // Lanes 0,8,16,24 write 4 contiguous floats -> 1 wavefront.
        if (valid && sl == 0) out[e] = acc;

        if (!more) break;
        q = qn; e = en; valid = vn; s = sn; d = dn; t = tn;
    }
}

extern "C" void kernel_launch(void* const* d_in, const int* in_sizes, int n_in,
                              void* d_out, int out_size)
{
    const float* h       = (const float*)d_in[0];
    const int*   src     = (const int*)d_in[1];
    const int*   dst     = (const int*)d_in[2];
    const int*   etype   = (const int*)d_in[3];
    const float* fwd_rel = (const float*)d_in[4];
    // d_in[5] = rev_rel, unused in forward scoring.
    float* out = (float*)d_out;

    const int n_edges = in_sizes[1];   // src element count

    // One resident wave: GB300 has 152 SMs, 7 blocks/SM at 256 threads.
    const int threads = 256;
    int blocks = 152 * 7;
    const int nquads = (n_edges + 3) / 4;
    const int max_warps_needed = nquads;          // one quad per warp minimum
    const int max_blocks_needed = (max_warps_needed + 7) / 8;
    if (blocks > max_blocks_needed) blocks = max_blocks_needed;

    distmult_score_kernel<<<blocks, threads>>>(h, src, dst, etype, fwd_rel,
                                               out, n_edges);
}